// round 2
// baseline (speedup 1.0000x reference)
#include <cuda_runtime.h>

#define CCH 32
#define HH 128
#define WW 128
#define NPTS 262144
#define PLANE_ELEMS (HH * WW * CCH)   // 524288 floats per plane (transposed layout)

// Transposed triplanes: (plane, y, x, c) -- 6.3 MB, L2-resident
__device__ float g_tp[3 * PLANE_ELEMS];
// Sampled features in (b, c, pos) layout; MLP row r reads g_sampled[r*32 .. r*32+31]
__device__ float g_sampled[4 * CCH * NPTS];   // 134 MB

// ---------------------------------------------------------------------------
// K1: transpose (3*C, H, W) -> (3, H, W, C)
// ---------------------------------------------------------------------------
__global__ void transpose_kernel(const float* __restrict__ tri) {
    int t = blockIdx.x * blockDim.x + threadIdx.x;   // 0 .. 3*H*W
    if (t >= 3 * HH * WW) return;
    int p  = t / (HH * WW);
    int yx = t - p * (HH * WW);
    const float* src = tri + (size_t)p * CCH * HH * WW + yx;
    float v[CCH];
#pragma unroll
    for (int c = 0; c < CCH; c++) v[c] = src[(size_t)c * HH * WW];
    float4* dst = (float4*)(g_tp + (size_t)t * CCH);
#pragma unroll
    for (int k = 0; k < 8; k++)
        dst[k] = make_float4(v[4*k], v[4*k+1], v[4*k+2], v[4*k+3]);
}

// ---------------------------------------------------------------------------
// K2: bilinear sample 3 planes, accumulate 32 channels, write (b,c,pos)
// ---------------------------------------------------------------------------
__device__ __forceinline__ void sample_plane(const float* __restrict__ plane,
                                             float gx, float gy, float* acc) {
    // matches F.grid_sample(align_corners=True, padding_mode='zeros')
    float x = (gx + 1.0f) * 0.5f * (WW - 1);
    float y = (gy + 1.0f) * 0.5f * (HH - 1);
    float x0f = floorf(x), y0f = floorf(y);
    float wx = x - x0f,   wy = y - y0f;
    int x0 = (int)x0f, y0 = (int)y0f;
    int x1 = x0 + 1,   y1 = y0 + 1;

    float vx[2], vy[2];
    vx[0] = (x0 >= 0 && x0 < WW) ? 1.0f : 0.0f;
    vx[1] = (x1 >= 0 && x1 < WW) ? 1.0f : 0.0f;
    vy[0] = (y0 >= 0 && y0 < HH) ? 1.0f : 0.0f;
    vy[1] = (y1 >= 0 && y1 < HH) ? 1.0f : 0.0f;

    int xi[2], yi[2];
    xi[0] = min(max(x0, 0), WW - 1);
    xi[1] = min(max(x1, 0), WW - 1);
    yi[0] = min(max(y0, 0), HH - 1);
    yi[1] = min(max(y1, 0), HH - 1);

    float wxs[2] = {1.0f - wx, wx};
    float wys[2] = {1.0f - wy, wy};

#pragma unroll
    for (int cy = 0; cy < 2; cy++) {
#pragma unroll
        for (int cx = 0; cx < 2; cx++) {
            float w = (wxs[cx] * wys[cy]) * (vx[cx] * vy[cy]);
            const float4* p4 =
                (const float4*)(plane + (size_t)(yi[cy] * WW + xi[cx]) * CCH);
#pragma unroll
            for (int k = 0; k < 8; k++) {
                float4 v = __ldg(p4 + k);
                acc[4*k+0] = fmaf(w, v.x, acc[4*k+0]);
                acc[4*k+1] = fmaf(w, v.y, acc[4*k+1]);
                acc[4*k+2] = fmaf(w, v.z, acc[4*k+2]);
                acc[4*k+3] = fmaf(w, v.w, acc[4*k+3]);
            }
        }
    }
}

__global__ void sample_kernel(const float* __restrict__ coords, int total) {
    int t = blockIdx.x * blockDim.x + threadIdx.x;
    if (t >= total) return;
    float gx = coords[3*t + 0];
    float gy = coords[3*t + 1];
    float gz = coords[3*t + 2];

    float acc[CCH];
#pragma unroll
    for (int c = 0; c < CCH; c++) acc[c] = 0.0f;

    // Reference split order: plane0 = feat_xy, plane1 = feat_yz, plane2 = feat_xz
    sample_plane(g_tp,                   gx, gy, acc);   // feat_xy(x, y)
    sample_plane(g_tp + 2 * PLANE_ELEMS, gx, gz, acc);   // feat_xz(x, z)
    sample_plane(g_tp +     PLANE_ELEMS, gy, gz, acc);   // feat_yz(y, z)

    int b   = t >> 18;            // / NPTS
    int pos = t & (NPTS - 1);
    float* out = g_sampled + (size_t)b * CCH * NPTS + pos;
#pragma unroll
    for (int c = 0; c < CCH; c++) out[(size_t)c * NPTS] = acc[c];
}

// ---------------------------------------------------------------------------
// K3: MLP 32 -> 128 -> 128 -> 4 (relu each), output permute [1,2,3,0]
// ---------------------------------------------------------------------------
__global__ void __launch_bounds__(256, 1)
mlp_kernel(const float* __restrict__ w0, const float* __restrict__ b0,
           const float* __restrict__ w1, const float* __restrict__ b1,
           const float* __restrict__ w2, const float* __restrict__ b2,
           float* __restrict__ out, int total) {
    extern __shared__ float smem[];
    float* s_w0  = smem;             // 128*32 = 4096
    float* s_w1t = smem + 4096;      // 128*128 = 16384 (transposed: [c][j])
    float* s_w2  = smem + 20480;     // 4*128 = 512
    float* s_b0  = smem + 20992;     // 128
    float* s_b1  = smem + 21120;     // 128
    float* s_b2  = smem + 21248;     // 4

    int tid = threadIdx.x;
    for (int i = tid; i < 4096;  i += 256) s_w0[i] = w0[i];
    for (int i = tid; i < 16384; i += 256) s_w1t[i] = w1[(i & 127) * 128 + (i >> 7)];
    for (int i = tid; i < 512;   i += 256) s_w2[i] = w2[i];
    if (tid < 128) { s_b0[tid] = b0[tid]; s_b1[tid] = b1[tid]; }
    if (tid < 4)   { s_b2[tid] = b2[tid]; }
    __syncthreads();

    int stride = gridDim.x * blockDim.x;
    for (int r = blockIdx.x * blockDim.x + tid; r < total; r += stride) {
        const float4* f4 = (const float4*)(g_sampled + (size_t)r * CCH);
        float feats[32];
#pragma unroll
        for (int k = 0; k < 8; k++) {
            float4 v = f4[k];
            feats[4*k+0] = v.x; feats[4*k+1] = v.y;
            feats[4*k+2] = v.z; feats[4*k+3] = v.w;
        }

        float h1[128];
#pragma unroll
        for (int j = 0; j < 128; j++) h1[j] = s_b1[j];

#pragma unroll 1
        for (int c = 0; c < 128; c++) {
            const float4* wr = (const float4*)(s_w0 + c * 32);
            float a0 = s_b0[c], a1 = 0.0f, a2 = 0.0f, a3 = 0.0f;
#pragma unroll
            for (int k = 0; k < 8; k++) {
                float4 w = wr[k];
                a0 = fmaf(feats[4*k+0], w.x, a0);
                a1 = fmaf(feats[4*k+1], w.y, a1);
                a2 = fmaf(feats[4*k+2], w.z, a2);
                a3 = fmaf(feats[4*k+3], w.w, a3);
            }
            float t = fmaxf((a0 + a1) + (a2 + a3), 0.0f);

            const float4* w1r = (const float4*)(s_w1t + c * 128);
#pragma unroll
            for (int j = 0; j < 32; j++) {
                float4 w = w1r[j];
                h1[4*j+0] = fmaf(t, w.x, h1[4*j+0]);
                h1[4*j+1] = fmaf(t, w.y, h1[4*j+1]);
                h1[4*j+2] = fmaf(t, w.z, h1[4*j+2]);
                h1[4*j+3] = fmaf(t, w.w, h1[4*j+3]);
            }
        }

#pragma unroll
        for (int j = 0; j < 128; j++) h1[j] = fmaxf(h1[j], 0.0f);

        float o[4];
#pragma unroll
        for (int k = 0; k < 4; k++) {
            const float4* w2r = (const float4*)(s_w2 + k * 128);
            float a0 = s_b2[k], a1 = 0.0f, a2 = 0.0f, a3 = 0.0f;
#pragma unroll
            for (int j = 0; j < 32; j++) {
                float4 w = w2r[j];
                a0 = fmaf(h1[4*j+0], w.x, a0);
                a1 = fmaf(h1[4*j+1], w.y, a1);
                a2 = fmaf(h1[4*j+2], w.z, a2);
                a3 = fmaf(h1[4*j+3], w.w, a3);
            }
            o[k] = fmaxf((a0 + a1) + (a2 + a3), 0.0f);
        }

        // raw = concat(net[...,1:4], net[...,0:1])
        ((float4*)out)[r] = make_float4(o[1], o[2], o[3], o[0]);
    }
}

// ---------------------------------------------------------------------------
extern "C" void kernel_launch(void* const* d_in, const int* in_sizes, int n_in,
                              void* d_out, int out_size) {
    const float* coords = (const float*)d_in[0];
    const float* tri    = (const float*)d_in[1];
    const float* w0     = (const float*)d_in[2];
    const float* b0     = (const float*)d_in[3];
    const float* w1     = (const float*)d_in[4];
    const float* b1     = (const float*)d_in[5];
    const float* w2     = (const float*)d_in[6];
    const float* b2     = (const float*)d_in[7];
    float* out = (float*)d_out;

    int total = in_sizes[0] / 3;   // B * N points = MLP rows

    transpose_kernel<<<(3 * HH * WW + 127) / 128, 128>>>(tri);
    sample_kernel<<<(total + 255) / 256, 256>>>(coords, total);

    static int mlp_smem = (21248 + 8) * 4;   // ~85 KB dynamic shared
    cudaFuncSetAttribute(mlp_kernel,
                         cudaFuncAttributeMaxDynamicSharedMemorySize, mlp_smem);
    mlp_kernel<<<296, 256, mlp_smem>>>(w0, b0, w1, b1, w2, b2, out, total);
}

// round 3
// speedup vs baseline: 1.0579x; 1.0579x over previous
#include <cuda_runtime.h>

#define CCH 32
#define HH 128
#define WW 128
#define NPTS 262144
#define PLANE_ELEMS (HH * WW * CCH)

typedef unsigned long long ull;

// Transposed triplanes: (plane, y, x, c) -- 6.3 MB, L2-resident
__device__ float g_tp[3 * PLANE_ELEMS];
// Sampled features in (b, c, pos) layout; MLP row r reads g_sampled[r*32 .. r*32+31]
__device__ float g_sampled[4 * CCH * NPTS];   // 134 MB

// ---------------------------------------------------------------------------
// packed f32x2 helpers (Blackwell-only PTX; 2 fp32 FMAs per instruction)
// ---------------------------------------------------------------------------
__device__ __forceinline__ ull fma2(ull a, ull b, ull c) {
    ull d;
    asm("fma.rn.f32x2 %0, %1, %2, %3;" : "=l"(d) : "l"(a), "l"(b), "l"(c));
    return d;
}
__device__ __forceinline__ ull pack2(float lo, float hi) {
    ull r;
    asm("mov.b64 %0, {%1, %2};" : "=l"(r) : "f"(lo), "f"(hi));
    return r;
}
__device__ __forceinline__ void unpack2(ull v, float& lo, float& hi) {
    asm("mov.b64 {%0, %1}, %2;" : "=f"(lo), "=f"(hi) : "l"(v));
}

// ---------------------------------------------------------------------------
// K1: transpose (3*C, H, W) -> (3, H, W, C)
// ---------------------------------------------------------------------------
__global__ void transpose_kernel(const float* __restrict__ tri) {
    int t = blockIdx.x * blockDim.x + threadIdx.x;   // 0 .. 3*H*W
    if (t >= 3 * HH * WW) return;
    int p  = t / (HH * WW);
    int yx = t - p * (HH * WW);
    const float* src = tri + (size_t)p * CCH * HH * WW + yx;
    float v[CCH];
#pragma unroll
    for (int c = 0; c < CCH; c++) v[c] = src[(size_t)c * HH * WW];
    float4* dst = (float4*)(g_tp + (size_t)t * CCH);
#pragma unroll
    for (int k = 0; k < 8; k++)
        dst[k] = make_float4(v[4*k], v[4*k+1], v[4*k+2], v[4*k+3]);
}

// ---------------------------------------------------------------------------
// K2: bilinear sample 3 planes, accumulate 32 channels, write (b,c,pos)
// ---------------------------------------------------------------------------
__device__ __forceinline__ void sample_plane(const float* __restrict__ plane,
                                             float gx, float gy, float* acc) {
    float x = (gx + 1.0f) * 0.5f * (WW - 1);
    float y = (gy + 1.0f) * 0.5f * (HH - 1);
    float x0f = floorf(x), y0f = floorf(y);
    float wx = x - x0f,   wy = y - y0f;
    int x0 = (int)x0f, y0 = (int)y0f;
    int x1 = x0 + 1,   y1 = y0 + 1;

    float vx[2], vy[2];
    vx[0] = (x0 >= 0 && x0 < WW) ? 1.0f : 0.0f;
    vx[1] = (x1 >= 0 && x1 < WW) ? 1.0f : 0.0f;
    vy[0] = (y0 >= 0 && y0 < HH) ? 1.0f : 0.0f;
    vy[1] = (y1 >= 0 && y1 < HH) ? 1.0f : 0.0f;

    int xi[2], yi[2];
    xi[0] = min(max(x0, 0), WW - 1);
    xi[1] = min(max(x1, 0), WW - 1);
    yi[0] = min(max(y0, 0), HH - 1);
    yi[1] = min(max(y1, 0), HH - 1);

    float wxs[2] = {1.0f - wx, wx};
    float wys[2] = {1.0f - wy, wy};

#pragma unroll
    for (int cy = 0; cy < 2; cy++) {
#pragma unroll
        for (int cx = 0; cx < 2; cx++) {
            float w = (wxs[cx] * wys[cy]) * (vx[cx] * vy[cy]);
            const float4* p4 =
                (const float4*)(plane + (size_t)(yi[cy] * WW + xi[cx]) * CCH);
#pragma unroll
            for (int k = 0; k < 8; k++) {
                float4 v = __ldg(p4 + k);
                acc[4*k+0] = fmaf(w, v.x, acc[4*k+0]);
                acc[4*k+1] = fmaf(w, v.y, acc[4*k+1]);
                acc[4*k+2] = fmaf(w, v.z, acc[4*k+2]);
                acc[4*k+3] = fmaf(w, v.w, acc[4*k+3]);
            }
        }
    }
}

__global__ void sample_kernel(const float* __restrict__ coords, int total) {
    int t = blockIdx.x * blockDim.x + threadIdx.x;
    if (t >= total) return;
    float gx = coords[3*t + 0];
    float gy = coords[3*t + 1];
    float gz = coords[3*t + 2];

    float acc[CCH];
#pragma unroll
    for (int c = 0; c < CCH; c++) acc[c] = 0.0f;

    // split order: plane0 = feat_xy, plane1 = feat_yz, plane2 = feat_xz
    sample_plane(g_tp,                   gx, gy, acc);   // feat_xy(x, y)
    sample_plane(g_tp + 2 * PLANE_ELEMS, gx, gz, acc);   // feat_xz(x, z)
    sample_plane(g_tp +     PLANE_ELEMS, gy, gz, acc);   // feat_yz(y, z)

    int b   = t >> 18;
    int pos = t & (NPTS - 1);
    float* out = g_sampled + (size_t)b * CCH * NPTS + pos;
#pragma unroll
    for (int c = 0; c < CCH; c++) out[(size_t)c * NPTS] = acc[c];
}

// ---------------------------------------------------------------------------
// K3: MLP 32 -> 128 -> 128 -> 4 with packed f32x2 FMA (bit-exact vs fmaf)
// ---------------------------------------------------------------------------
__global__ void __launch_bounds__(128, 2)
mlp_kernel(const float* __restrict__ w0, const float* __restrict__ b0,
           const float* __restrict__ w1, const float* __restrict__ b1,
           const float* __restrict__ w2, const float* __restrict__ b2,
           float* __restrict__ out, int total) {
    extern __shared__ float smem[];
    float* s_w0  = smem;             // 128*32 = 4096
    float* s_w1t = smem + 4096;      // 128*128 = 16384 (transposed: [c][j])
    float* s_w2  = smem + 20480;     // 4*128 = 512
    float* s_b0  = smem + 20992;     // 128
    float* s_b1  = smem + 21120;     // 128
    float* s_b2  = smem + 21248;     // 4

    int tid = threadIdx.x;
    for (int i = tid; i < 4096;  i += 128) s_w0[i] = w0[i];
    for (int i = tid; i < 16384; i += 128) s_w1t[i] = w1[(i & 127) * 128 + (i >> 7)];
    for (int i = tid; i < 512;   i += 128) s_w2[i] = w2[i];
    if (tid < 128) { s_b0[tid] = b0[tid]; s_b1[tid] = b1[tid]; }
    if (tid < 4)   { s_b2[tid] = b2[tid]; }
    __syncthreads();

    int stride = gridDim.x * blockDim.x;
    for (int r = blockIdx.x * blockDim.x + tid; r < total; r += stride) {
        // contiguous 32-float feature row -> 16 packed pairs
        const ulonglong2* f2 = (const ulonglong2*)(g_sampled + (size_t)r * CCH);
        ull feats[16];
#pragma unroll
        for (int k = 0; k < 8; k++) {
            ulonglong2 v = f2[k];
            feats[2*k]   = v.x;
            feats[2*k+1] = v.y;
        }

        // h1 as 64 packed pairs, init = b1
        ull h1[64];
        const ulonglong2* b1p = (const ulonglong2*)s_b1;
#pragma unroll
        for (int j = 0; j < 32; j++) {
            ulonglong2 v = b1p[j];
            h1[2*j]   = v.x;
            h1[2*j+1] = v.y;
        }

#pragma unroll 1
        for (int c = 0; c < 128; c++) {
            // ---- layer0: t = relu(b0[c] + feats . w0[c,:]) ----
            const ulonglong2* wr = (const ulonglong2*)(s_w0 + c * 32);
            ull a0 = 0, a1 = 0, a2 = 0, a3 = 0;
#pragma unroll
            for (int q = 0; q < 4; q++) {
                ulonglong2 wA = wr[2*q];
                ulonglong2 wB = wr[2*q+1];
                a0 = fma2(feats[4*q+0], wA.x, a0);
                a1 = fma2(feats[4*q+1], wA.y, a1);
                a2 = fma2(feats[4*q+2], wB.x, a2);
                a3 = fma2(feats[4*q+3], wB.y, a3);
            }
            float p0, p1, p2, p3, p4, p5, p6, p7;
            unpack2(a0, p0, p1);
            unpack2(a1, p2, p3);
            unpack2(a2, p4, p5);
            unpack2(a3, p6, p7);
            float t = s_b0[c] + ((p0 + p1) + (p2 + p3)) + ((p4 + p5) + (p6 + p7));
            t = fmaxf(t, 0.0f);
            ull tt = pack2(t, t);

            // ---- layer1: h1 += t * w1[:, c] (64 packed FMA2) ----
            const ulonglong2* w1r = (const ulonglong2*)(s_w1t + c * 128);
#pragma unroll
            for (int j = 0; j < 32; j++) {
                ulonglong2 w = w1r[j];
                h1[2*j]   = fma2(tt, w.x, h1[2*j]);
                h1[2*j+1] = fma2(tt, w.y, h1[2*j+1]);
            }
        }

        // relu h1 (packed, via unpack/repack)
#pragma unroll
        for (int j = 0; j < 64; j++) {
            float lo, hi;
            unpack2(h1[j], lo, hi);
            h1[j] = pack2(fmaxf(lo, 0.0f), fmaxf(hi, 0.0f));
        }

        // ---- layer2: 4 outputs ----
        float o[4];
#pragma unroll
        for (int k = 0; k < 4; k++) {
            const ulonglong2* w2r = (const ulonglong2*)(s_w2 + k * 128);
            ull a0 = 0, a1 = 0, a2 = 0, a3 = 0;
#pragma unroll
            for (int j = 0; j < 16; j++) {
                ulonglong2 wA = w2r[2*j];
                ulonglong2 wB = w2r[2*j+1];
                a0 = fma2(h1[4*j+0], wA.x, a0);
                a1 = fma2(h1[4*j+1], wA.y, a1);
                a2 = fma2(h1[4*j+2], wB.x, a2);
                a3 = fma2(h1[4*j+3], wB.y, a3);
            }
            float p0, p1, p2, p3, p4, p5, p6, p7;
            unpack2(a0, p0, p1);
            unpack2(a1, p2, p3);
            unpack2(a2, p4, p5);
            unpack2(a3, p6, p7);
            float v = s_b2[k] + ((p0 + p1) + (p2 + p3)) + ((p4 + p5) + (p6 + p7));
            o[k] = fmaxf(v, 0.0f);
        }

        // raw = concat(net[...,1:4], net[...,0:1])
        ((float4*)out)[r] = make_float4(o[1], o[2], o[3], o[0]);
    }
}

// ---------------------------------------------------------------------------
extern "C" void kernel_launch(void* const* d_in, const int* in_sizes, int n_in,
                              void* d_out, int out_size) {
    const float* coords = (const float*)d_in[0];
    const float* tri    = (const float*)d_in[1];
    const float* w0     = (const float*)d_in[2];
    const float* b0     = (const float*)d_in[3];
    const float* w1     = (const float*)d_in[4];
    const float* b1     = (const float*)d_in[5];
    const float* w2     = (const float*)d_in[6];
    const float* b2     = (const float*)d_in[7];
    float* out = (float*)d_out;

    int total = in_sizes[0] / 3;   // B * N points = MLP rows

    transpose_kernel<<<(3 * HH * WW + 127) / 128, 128>>>(tri);
    sample_kernel<<<(total + 255) / 256, 256>>>(coords, total);

    int mlp_smem = (21252 + 12) * 4;   // ~85 KB dynamic shared
    cudaFuncSetAttribute(mlp_kernel,
                         cudaFuncAttributeMaxDynamicSharedMemorySize, mlp_smem);
    mlp_kernel<<<296, 128, mlp_smem>>>(w0, b0, w1, b1, w2, b2, out, total);
}

// round 4
// speedup vs baseline: 1.7694x; 1.6727x over previous
#include <cuda_runtime.h>

#define CCH 32
#define HH 128
#define WW 128
#define NPTS 262144
#define PLANE_ELEMS (HH * WW * CCH)

typedef unsigned long long ull;

// Transposed triplanes: (plane, y, x, c) -- 6.3 MB, L2-resident
__device__ float g_tp[3 * PLANE_ELEMS];
// Sampled features (b, c, pos) flat; MLP row r = g_sampled[r*32 .. r*32+31]
__device__ float g_sampled[4 * CCH * NPTS];   // 134 MB

// ---------------------------------------------------------------------------
// packed f32x2 helpers
// ---------------------------------------------------------------------------
__device__ __forceinline__ ull fma2(ull a, ull b, ull c) {
    ull d;
    asm("fma.rn.f32x2 %0, %1, %2, %3;" : "=l"(d) : "l"(a), "l"(b), "l"(c));
    return d;
}
__device__ __forceinline__ ull pack2(float lo, float hi) {
    ull r;
    asm("mov.b64 %0, {%1, %2};" : "=l"(r) : "f"(lo), "f"(hi));
    return r;
}
__device__ __forceinline__ void unpack2(ull v, float& lo, float& hi) {
    asm("mov.b64 {%0, %1}, %2;" : "=f"(lo), "=f"(hi) : "l"(v));
}

// ---------------------------------------------------------------------------
// K1: transpose (3*C, H, W) -> (3, H, W, C)
// ---------------------------------------------------------------------------
__global__ void transpose_kernel(const float* __restrict__ tri) {
    int t = blockIdx.x * blockDim.x + threadIdx.x;
    if (t >= 3 * HH * WW) return;
    int p  = t / (HH * WW);
    int yx = t - p * (HH * WW);
    const float* src = tri + (size_t)p * CCH * HH * WW + yx;
    float v[CCH];
#pragma unroll
    for (int c = 0; c < CCH; c++) v[c] = src[(size_t)c * HH * WW];
    float4* dst = (float4*)(g_tp + (size_t)t * CCH);
#pragma unroll
    for (int k = 0; k < 8; k++)
        dst[k] = make_float4(v[4*k], v[4*k+1], v[4*k+2], v[4*k+3]);
}

// ---------------------------------------------------------------------------
// K2: bilinear sample 3 planes, accumulate 32 channels, write (b,c,pos)
// ---------------------------------------------------------------------------
__device__ __forceinline__ void sample_plane(const float* __restrict__ plane,
                                             float gx, float gy, float* acc) {
    float x = (gx + 1.0f) * 0.5f * (WW - 1);
    float y = (gy + 1.0f) * 0.5f * (HH - 1);
    float x0f = floorf(x), y0f = floorf(y);
    float wx = x - x0f,   wy = y - y0f;
    int x0 = (int)x0f, y0 = (int)y0f;
    int x1 = x0 + 1,   y1 = y0 + 1;

    float vx[2], vy[2];
    vx[0] = (x0 >= 0 && x0 < WW) ? 1.0f : 0.0f;
    vx[1] = (x1 >= 0 && x1 < WW) ? 1.0f : 0.0f;
    vy[0] = (y0 >= 0 && y0 < HH) ? 1.0f : 0.0f;
    vy[1] = (y1 >= 0 && y1 < HH) ? 1.0f : 0.0f;

    int xi[2], yi[2];
    xi[0] = min(max(x0, 0), WW - 1);
    xi[1] = min(max(x1, 0), WW - 1);
    yi[0] = min(max(y0, 0), HH - 1);
    yi[1] = min(max(y1, 0), HH - 1);

    float wxs[2] = {1.0f - wx, wx};
    float wys[2] = {1.0f - wy, wy};

#pragma unroll
    for (int cy = 0; cy < 2; cy++) {
#pragma unroll
        for (int cx = 0; cx < 2; cx++) {
            float w = (wxs[cx] * wys[cy]) * (vx[cx] * vy[cy]);
            const float4* p4 =
                (const float4*)(plane + (size_t)(yi[cy] * WW + xi[cx]) * CCH);
#pragma unroll
            for (int k = 0; k < 8; k++) {
                float4 v = __ldg(p4 + k);
                acc[4*k+0] = fmaf(w, v.x, acc[4*k+0]);
                acc[4*k+1] = fmaf(w, v.y, acc[4*k+1]);
                acc[4*k+2] = fmaf(w, v.z, acc[4*k+2]);
                acc[4*k+3] = fmaf(w, v.w, acc[4*k+3]);
            }
        }
    }
}

__global__ void sample_kernel(const float* __restrict__ coords, int total) {
    int t = blockIdx.x * blockDim.x + threadIdx.x;
    if (t >= total) return;
    float gx = coords[3*t + 0];
    float gy = coords[3*t + 1];
    float gz = coords[3*t + 2];

    float acc[CCH];
#pragma unroll
    for (int c = 0; c < CCH; c++) acc[c] = 0.0f;

    // split order: plane0 = feat_xy, plane1 = feat_yz, plane2 = feat_xz
    sample_plane(g_tp,                   gx, gy, acc);   // feat_xy(x, y)
    sample_plane(g_tp + 2 * PLANE_ELEMS, gx, gz, acc);   // feat_xz(x, z)
    sample_plane(g_tp +     PLANE_ELEMS, gy, gz, acc);   // feat_yz(y, z)

    int b   = t >> 18;
    int pos = t & (NPTS - 1);
    float* out = g_sampled + (size_t)b * CCH * NPTS + pos;
#pragma unroll
    for (int c = 0; c < CCH; c++) out[(size_t)c * NPTS] = acc[c];
}

// ---------------------------------------------------------------------------
// K3: tiled MLP 32 -> 128 -> 128 -> 4.
// CTA = 256 threads, tile = 128 rows. Thread tile = 4 rows x 16 cols.
// warp cg = tid>>5 owns cols [cg*16, cg*16+16); lane owns rows [4*lane, 4*lane+4).
// ---------------------------------------------------------------------------
#define NROWS_TILE 128
// smem float offsets
#define OFF_W1T 0          // 16384  : s_w1t[c*128 + j] = w1[j][c]
#define OFF_W0T 16384      // 4096   : s_w0t[k*128 + c] = w0[c][k]
#define OFF_W2  20480      // 512    : w2[kk*128 + j]
#define OFF_B0  20992      // 128
#define OFF_B1  21120      // 128
#define OFF_B2  21248      // 4 (pad to 16)
#define OFF_FT  21264      // 4096   : s_ft[k*128 + row]
#define OFF_H0  25360      // 16384  : s_h0[c*128 + row]
#define OFF_RED 41744      // 4096   : s_red[(cg*128 + row)*4 + kk]
#define SMEM_FLOATS 45840

__global__ void __launch_bounds__(256, 1)
mlp_kernel(const float* __restrict__ w0, const float* __restrict__ b0,
           const float* __restrict__ w1, const float* __restrict__ b1,
           const float* __restrict__ w2, const float* __restrict__ b2,
           float* __restrict__ out, int total) {
    extern __shared__ float smem[];
    float* s_w1t = smem + OFF_W1T;
    float* s_w0t = smem + OFF_W0T;
    float* s_w2  = smem + OFF_W2;
    float* s_b0  = smem + OFF_B0;
    float* s_b1  = smem + OFF_B1;
    float* s_b2  = smem + OFF_B2;
    float* s_ft  = smem + OFF_FT;
    float* s_h0  = smem + OFF_H0;
    float* s_red = smem + OFF_RED;

    int tid = threadIdx.x;
    for (int i = tid; i < 16384; i += 256) s_w1t[i] = w1[(i & 127) * 128 + (i >> 7)];
    for (int i = tid; i < 4096;  i += 256) s_w0t[i] = w0[(i & 127) * 32  + (i >> 7)];
    for (int i = tid; i < 512;   i += 256) s_w2[i] = w2[i];
    if (tid < 128) { s_b0[tid] = b0[tid]; s_b1[tid] = b1[tid]; }
    if (tid < 4)   { s_b2[tid] = b2[tid]; }
    __syncthreads();

    int lane = tid & 31;
    int cg   = tid >> 5;          // 0..7
    int c0   = cg * 16;
    int r0   = 4 * lane;

    // b1 init pairs for this thread's 16 cols
    ull binit[8];
    {
        const ulonglong2* b1v = (const ulonglong2*)(s_b1 + c0);
#pragma unroll
        for (int i = 0; i < 4; i++) {
            ulonglong2 v = b1v[i];
            binit[2*i]   = v.x;
            binit[2*i+1] = v.y;
        }
    }

    int ntiles = total / NROWS_TILE;
    for (int tile = blockIdx.x; tile < ntiles; tile += gridDim.x) {
        int rowBase = tile * NROWS_TILE;

        // ---- stage feats transposed: s_ft[k*128 + row] ----
        {
            int row = tid >> 1;
            int k0  = (tid & 1) * 16;
            const float4* src =
                (const float4*)(g_sampled + (size_t)(rowBase + row) * 32 + k0);
#pragma unroll
            for (int q = 0; q < 4; q++) {
                float4 v = src[q];
                int k = k0 + 4*q;
                s_ft[(k+0)*128 + row] = v.x;
                s_ft[(k+1)*128 + row] = v.y;
                s_ft[(k+2)*128 + row] = v.z;
                s_ft[(k+3)*128 + row] = v.w;
            }
        }
        __syncthreads();

        // ---- phase1: h0 = relu(feats @ w0^T + b0), tile 128x128 ----
        {
            ull acc[4][8];
#pragma unroll
            for (int r = 0; r < 4; r++)
#pragma unroll
                for (int p = 0; p < 8; p++) acc[r][p] = 0ull;

#pragma unroll 4
            for (int k = 0; k < 32; k++) {
                float4 a = *(const float4*)(s_ft + k*128 + r0);
                ull a0 = pack2(a.x, a.x), a1 = pack2(a.y, a.y);
                ull a2 = pack2(a.z, a.z), a3 = pack2(a.w, a.w);
                const ulonglong2* wv = (const ulonglong2*)(s_w0t + k*128 + c0);
#pragma unroll
                for (int i = 0; i < 4; i++) {
                    ulonglong2 w = wv[i];
                    acc[0][2*i]   = fma2(a0, w.x, acc[0][2*i]);
                    acc[0][2*i+1] = fma2(a0, w.y, acc[0][2*i+1]);
                    acc[1][2*i]   = fma2(a1, w.x, acc[1][2*i]);
                    acc[1][2*i+1] = fma2(a1, w.y, acc[1][2*i+1]);
                    acc[2][2*i]   = fma2(a2, w.x, acc[2][2*i]);
                    acc[2][2*i+1] = fma2(a2, w.y, acc[2][2*i+1]);
                    acc[3][2*i]   = fma2(a3, w.x, acc[3][2*i]);
                    acc[3][2*i+1] = fma2(a3, w.y, acc[3][2*i+1]);
                }
            }
            // bias + relu + store transposed to s_h0[c*128 + row]
#pragma unroll
            for (int p = 0; p < 8; p++) {
                int c = c0 + 2*p;
                float blo = s_b0[c], bhi = s_b0[c+1];
                float lo[4], hi[4];
#pragma unroll
                for (int r = 0; r < 4; r++) {
                    float l, h;
                    unpack2(acc[r][p], l, h);
                    lo[r] = fmaxf(l + blo, 0.0f);
                    hi[r] = fmaxf(h + bhi, 0.0f);
                }
                *(float4*)(s_h0 + c*128 + r0)     = make_float4(lo[0], lo[1], lo[2], lo[3]);
                *(float4*)(s_h0 + (c+1)*128 + r0) = make_float4(hi[0], hi[1], hi[2], hi[3]);
            }
        }
        __syncthreads();

        // ---- phase2: h1 = relu(h0 @ w1^T + b1), tile 128x128 ----
        ull acc1[4][8];
#pragma unroll
        for (int r = 0; r < 4; r++)
#pragma unroll
            for (int p = 0; p < 8; p++) acc1[r][p] = binit[p];

#pragma unroll 4
        for (int k = 0; k < 128; k++) {
            float4 a = *(const float4*)(s_h0 + k*128 + r0);
            ull a0 = pack2(a.x, a.x), a1 = pack2(a.y, a.y);
            ull a2 = pack2(a.z, a.z), a3 = pack2(a.w, a.w);
            const ulonglong2* wv = (const ulonglong2*)(s_w1t + k*128 + c0);
#pragma unroll
            for (int i = 0; i < 4; i++) {
                ulonglong2 w = wv[i];
                acc1[0][2*i]   = fma2(a0, w.x, acc1[0][2*i]);
                acc1[0][2*i+1] = fma2(a0, w.y, acc1[0][2*i+1]);
                acc1[1][2*i]   = fma2(a1, w.x, acc1[1][2*i]);
                acc1[1][2*i+1] = fma2(a1, w.y, acc1[1][2*i+1]);
                acc1[2][2*i]   = fma2(a2, w.x, acc1[2][2*i]);
                acc1[2][2*i+1] = fma2(a2, w.y, acc1[2][2*i+1]);
                acc1[3][2*i]   = fma2(a3, w.x, acc1[3][2*i]);
                acc1[3][2*i+1] = fma2(a3, w.y, acc1[3][2*i+1]);
            }
        }

        // relu h1 (repack)
#pragma unroll
        for (int r = 0; r < 4; r++)
#pragma unroll
            for (int p = 0; p < 8; p++) {
                float l, h;
                unpack2(acc1[r][p], l, h);
                acc1[r][p] = pack2(fmaxf(l, 0.0f), fmaxf(h, 0.0f));
            }

        // ---- phase3: partial layer2 over this warp's 16 cols ----
        float part[4][4];
#pragma unroll
        for (int kk = 0; kk < 4; kk++) {
            const ulonglong2* w2v = (const ulonglong2*)(s_w2 + kk*128 + c0);
            ull wp[8];
#pragma unroll
            for (int i = 0; i < 4; i++) {
                ulonglong2 v = w2v[i];
                wp[2*i] = v.x; wp[2*i+1] = v.y;
            }
#pragma unroll
            for (int r = 0; r < 4; r++) {
                ull s0 = 0ull, s1 = 0ull;
#pragma unroll
                for (int p = 0; p < 4; p++) {
                    s0 = fma2(acc1[r][2*p],   wp[2*p],   s0);
                    s1 = fma2(acc1[r][2*p+1], wp[2*p+1], s1);
                }
                float a, b, c, d;
                unpack2(s0, a, b);
                unpack2(s1, c, d);
                part[r][kk] = (a + b) + (c + d);
            }
        }
#pragma unroll
        for (int r = 0; r < 4; r++)
            *(float4*)(s_red + (size_t)(cg*128 + r0 + r) * 4) =
                make_float4(part[r][0], part[r][1], part[r][2], part[r][3]);
        __syncthreads();

        // ---- reduce across 8 warps, relu, permute, store ----
        if (tid < 128) {
            float o0 = s_b2[0], o1 = s_b2[1], o2 = s_b2[2], o3 = s_b2[3];
#pragma unroll
            for (int g = 0; g < 8; g++) {
                float4 v = *(const float4*)(s_red + (size_t)(g*128 + tid) * 4);
                o0 += v.x; o1 += v.y; o2 += v.z; o3 += v.w;
            }
            o0 = fmaxf(o0, 0.0f); o1 = fmaxf(o1, 0.0f);
            o2 = fmaxf(o2, 0.0f); o3 = fmaxf(o3, 0.0f);
            // raw = concat(net[...,1:4], net[...,0:1])
            ((float4*)out)[rowBase + tid] = make_float4(o1, o2, o3, o0);
        }
        __syncthreads();
    }
}

// ---------------------------------------------------------------------------
extern "C" void kernel_launch(void* const* d_in, const int* in_sizes, int n_in,
                              void* d_out, int out_size) {
    const float* coords = (const float*)d_in[0];
    const float* tri    = (const float*)d_in[1];
    const float* w0     = (const float*)d_in[2];
    const float* b0     = (const float*)d_in[3];
    const float* w1     = (const float*)d_in[4];
    const float* b1     = (const float*)d_in[5];
    const float* w2     = (const float*)d_in[6];
    const float* b2     = (const float*)d_in[7];
    float* out = (float*)d_out;

    int total = in_sizes[0] / 3;   // B * N points = MLP rows

    transpose_kernel<<<(3 * HH * WW + 127) / 128, 128>>>(tri);
    sample_kernel<<<(total + 255) / 256, 256>>>(coords, total);

    int mlp_smem = SMEM_FLOATS * 4;   // ~179 KB dynamic shared
    cudaFuncSetAttribute(mlp_kernel,
                         cudaFuncAttributeMaxDynamicSharedMemorySize, mlp_smem);
    mlp_kernel<<<148, 256, mlp_smem>>>(w0, b0, w1, b1, w2, b2, out, total);
}

// round 7
// speedup vs baseline: 2.2821x; 1.2897x over previous
#include <cuda_runtime.h>

#define CCH 32
#define HH 128
#define WW 128
#define NPTS 262144
#define PLANE_ELEMS (HH * WW * CCH)

typedef unsigned long long ull;

// Transposed triplanes: (plane, y, x, c) -- 6.3 MB, L2-resident
__device__ float g_tp[3 * PLANE_ELEMS];
// Sampled features in (b, c, pos) layout; MLP row r reads flat [r*32 .. r*32+31]
__device__ float g_sampled[4 * CCH * NPTS];   // 134 MB

// ---------------------------------------------------------------------------
// packed f32x2 helpers
// ---------------------------------------------------------------------------
__device__ __forceinline__ ull fma2(ull a, ull b, ull c) {
    ull d;
    asm("fma.rn.f32x2 %0, %1, %2, %3;" : "=l"(d) : "l"(a), "l"(b), "l"(c));
    return d;
}
__device__ __forceinline__ ull pack2(float lo, float hi) {
    ull r;
    asm("mov.b64 %0, {%1, %2};" : "=l"(r) : "f"(lo), "f"(hi));
    return r;
}
__device__ __forceinline__ void unpack2(ull v, float& lo, float& hi) {
    asm("mov.b64 {%0, %1}, %2;" : "=f"(lo), "=f"(hi) : "l"(v));
}

// ---------------------------------------------------------------------------
// K1: transpose (3*C, H, W) -> (3, H, W, C)
// ---------------------------------------------------------------------------
__global__ void transpose_kernel(const float* __restrict__ tri) {
    int t = blockIdx.x * blockDim.x + threadIdx.x;
    if (t >= 3 * HH * WW) return;
    int p  = t / (HH * WW);
    int yx = t - p * (HH * WW);
    const float* src = tri + (size_t)p * CCH * HH * WW + yx;
    float v[CCH];
#pragma unroll
    for (int c = 0; c < CCH; c++) v[c] = src[(size_t)c * HH * WW];
    float4* dst = (float4*)(g_tp + (size_t)t * CCH);
#pragma unroll
    for (int k = 0; k < 8; k++)
        dst[k] = make_float4(v[4*k], v[4*k+1], v[4*k+2], v[4*k+3]);
}

// ---------------------------------------------------------------------------
// K2: cooperative sampler -- 8 threads per point (each owns 4 channels),
// smem-staged transpose so output lands in the required (b,c,pos) layout.
// ---------------------------------------------------------------------------
__device__ __forceinline__ void sample_plane_c(const float* __restrict__ plane,
                                               float gx, float gy, int s,
                                               float4& acc) {
    float x = (gx + 1.0f) * 0.5f * (WW - 1);
    float y = (gy + 1.0f) * 0.5f * (HH - 1);
    float x0f = floorf(x), y0f = floorf(y);
    float wx = x - x0f,   wy = y - y0f;
    int x0 = (int)x0f, y0 = (int)y0f;
    int x1 = x0 + 1,   y1 = y0 + 1;

    float vxa = (x0 >= 0 && x0 < WW) ? 1.0f : 0.0f;
    float vxb = (x1 >= 0 && x1 < WW) ? 1.0f : 0.0f;
    float vya = (y0 >= 0 && y0 < HH) ? 1.0f : 0.0f;
    float vyb = (y1 >= 0 && y1 < HH) ? 1.0f : 0.0f;

    int xa = min(max(x0, 0), WW - 1);
    int xb = min(max(x1, 0), WW - 1);
    int ya = min(max(y0, 0), HH - 1);
    int yb = min(max(y1, 0), HH - 1);

    float wxs[2] = {(1.0f - wx) * vxa, wx * vxb};
    float wys[2] = {(1.0f - wy) * vya, wy * vyb};
    int   xi[2]  = {xa, xb};
    int   yi[2]  = {ya, yb};

#pragma unroll
    for (int cy = 0; cy < 2; cy++) {
#pragma unroll
        for (int cx = 0; cx < 2; cx++) {
            float w = wxs[cx] * wys[cy];
            float4 v = __ldg((const float4*)(plane +
                         (size_t)(yi[cy] * WW + xi[cx]) * CCH) + s);
            acc.x = fmaf(w, v.x, acc.x);
            acc.y = fmaf(w, v.y, acc.y);
            acc.z = fmaf(w, v.z, acc.z);
            acc.w = fmaf(w, v.w, acc.w);
        }
    }
}

__global__ void __launch_bounds__(256)
sample_kernel(const float* __restrict__ coords) {
    __shared__ float st[32 * 33];      // 32 points x 32 channels, padded
    int tid = threadIdx.x;
    int pl  = tid >> 3;                // local point 0..31
    int s   = tid & 7;                 // float4 channel slice 0..7
    int pbase = blockIdx.x * 32;
    int p = pbase + pl;

    float gx = __ldg(coords + 3 * p + 0);
    float gy = __ldg(coords + 3 * p + 1);
    float gz = __ldg(coords + 3 * p + 2);

    float4 acc = make_float4(0.0f, 0.0f, 0.0f, 0.0f);
    // split order: plane0 = feat_xy, plane1 = feat_yz, plane2 = feat_xz
    sample_plane_c(g_tp,                   gx, gy, s, acc);   // feat_xy(x, y)
    sample_plane_c(g_tp + 2 * PLANE_ELEMS, gx, gz, s, acc);   // feat_xz(x, z)
    sample_plane_c(g_tp +     PLANE_ELEMS, gy, gz, s, acc);   // feat_yz(y, z)

    float* row = st + pl * 33 + 4 * s;
    row[0] = acc.x; row[1] = acc.y; row[2] = acc.z; row[3] = acc.w;
    __syncthreads();

    // write (b, c, pos): 32 consecutive pos per channel -> coalesced
    int b       = pbase >> 18;           // pbase / NPTS (blocks never straddle b)
    int posBase = pbase & (NPTS - 1);
    float* outb = g_sampled + (size_t)b * CCH * NPTS + posBase;
#pragma unroll
    for (int i = 0; i < 4; i++) {
        int idx = tid + 256 * i;         // 0..1023
        int c = idx >> 5;                // channel 0..31
        int q = idx & 31;                // local pos 0..31
        outb[(size_t)c * NPTS + q] = st[q * 33 + c];
    }
}

// ---------------------------------------------------------------------------
// K3: tiled MLP 32 -> 128 -> 128 -> 4 (unchanged from R4, proven).
// CTA = 256 threads, tile = 128 rows. Thread tile = 4 rows x 16 cols.
// ---------------------------------------------------------------------------
#define NROWS_TILE 128
#define OFF_W1T 0
#define OFF_W0T 16384
#define OFF_W2  20480
#define OFF_B0  20992
#define OFF_B1  21120
#define OFF_B2  21248
#define OFF_FT  21264
#define OFF_H0  25360
#define OFF_RED 41744
#define SMEM_FLOATS 45840

__global__ void __launch_bounds__(256, 1)
mlp_kernel(const float* __restrict__ w0, const float* __restrict__ b0,
           const float* __restrict__ w1, const float* __restrict__ b1,
           const float* __restrict__ w2, const float* __restrict__ b2,
           float* __restrict__ out, int total) {
    extern __shared__ float smem[];
    float* s_w1t = smem + OFF_W1T;
    float* s_w0t = smem + OFF_W0T;
    float* s_w2  = smem + OFF_W2;
    float* s_b0  = smem + OFF_B0;
    float* s_b1  = smem + OFF_B1;
    float* s_b2  = smem + OFF_B2;
    float* s_ft  = smem + OFF_FT;
    float* s_h0  = smem + OFF_H0;
    float* s_red = smem + OFF_RED;

    int tid = threadIdx.x;
    for (int i = tid; i < 16384; i += 256) s_w1t[i] = w1[(i & 127) * 128 + (i >> 7)];
    for (int i = tid; i < 4096;  i += 256) s_w0t[i] = w0[(i & 127) * 32  + (i >> 7)];
    for (int i = tid; i < 512;   i += 256) s_w2[i] = w2[i];
    if (tid < 128) { s_b0[tid] = b0[tid]; s_b1[tid] = b1[tid]; }
    if (tid < 4)   { s_b2[tid] = b2[tid]; }
    __syncthreads();

    int lane = tid & 31;
    int cg   = tid >> 5;
    int c0   = cg * 16;
    int r0   = 4 * lane;

    ull binit[8];
    {
        const ulonglong2* b1v = (const ulonglong2*)(s_b1 + c0);
#pragma unroll
        for (int i = 0; i < 4; i++) {
            ulonglong2 v = b1v[i];
            binit[2*i]   = v.x;
            binit[2*i+1] = v.y;
        }
    }

    int ntiles = total / NROWS_TILE;
    for (int tile = blockIdx.x; tile < ntiles; tile += gridDim.x) {
        int rowBase = tile * NROWS_TILE;

        // ---- stage feats transposed: s_ft[k*128 + row] ----
        {
            int row = tid >> 1;
            int k0  = (tid & 1) * 16;
            const float4* src =
                (const float4*)(g_sampled + (size_t)(rowBase + row) * 32 + k0);
#pragma unroll
            for (int q = 0; q < 4; q++) {
                float4 v = src[q];
                int k = k0 + 4*q;
                s_ft[(k+0)*128 + row] = v.x;
                s_ft[(k+1)*128 + row] = v.y;
                s_ft[(k+2)*128 + row] = v.z;
                s_ft[(k+3)*128 + row] = v.w;
            }
        }
        __syncthreads();

        // ---- phase1: h0 = relu(feats @ w0^T + b0) ----
        {
            ull acc[4][8];
#pragma unroll
            for (int r = 0; r < 4; r++)
#pragma unroll
                for (int p = 0; p < 8; p++) acc[r][p] = 0ull;

#pragma unroll 4
            for (int k = 0; k < 32; k++) {
                float4 a = *(const float4*)(s_ft + k*128 + r0);
                ull a0 = pack2(a.x, a.x), a1 = pack2(a.y, a.y);
                ull a2 = pack2(a.z, a.z), a3 = pack2(a.w, a.w);
                const ulonglong2* wv = (const ulonglong2*)(s_w0t + k*128 + c0);
#pragma unroll
                for (int i = 0; i < 4; i++) {
                    ulonglong2 w = wv[i];
                    acc[0][2*i]   = fma2(a0, w.x, acc[0][2*i]);
                    acc[0][2*i+1] = fma2(a0, w.y, acc[0][2*i+1]);
                    acc[1][2*i]   = fma2(a1, w.x, acc[1][2*i]);
                    acc[1][2*i+1] = fma2(a1, w.y, acc[1][2*i+1]);
                    acc[2][2*i]   = fma2(a2, w.x, acc[2][2*i]);
                    acc[2][2*i+1] = fma2(a2, w.y, acc[2][2*i+1]);
                    acc[3][2*i]   = fma2(a3, w.x, acc[3][2*i]);
                    acc[3][2*i+1] = fma2(a3, w.y, acc[3][2*i+1]);
                }
            }
#pragma unroll
            for (int p = 0; p < 8; p++) {
                int c = c0 + 2*p;
                float blo = s_b0[c], bhi = s_b0[c+1];
                float lo[4], hi[4];
#pragma unroll
                for (int r = 0; r < 4; r++) {
                    float l, h;
                    unpack2(acc[r][p], l, h);
                    lo[r] = fmaxf(l + blo, 0.0f);
                    hi[r] = fmaxf(h + bhi, 0.0f);
                }
                *(float4*)(s_h0 + c*128 + r0)     = make_float4(lo[0], lo[1], lo[2], lo[3]);
                *(float4*)(s_h0 + (c+1)*128 + r0) = make_float4(hi[0], hi[1], hi[2], hi[3]);
            }
        }
        __syncthreads();

        // ---- phase2: h1 = relu(h0 @ w1^T + b1) ----
        ull acc1[4][8];
#pragma unroll
        for (int r = 0; r < 4; r++)
#pragma unroll
            for (int p = 0; p < 8; p++) acc1[r][p] = binit[p];

#pragma unroll 4
        for (int k = 0; k < 128; k++) {
            float4 a = *(const float4*)(s_h0 + k*128 + r0);
            ull a0 = pack2(a.x, a.x), a1 = pack2(a.y, a.y);
            ull a2 = pack2(a.z, a.z), a3 = pack2(a.w, a.w);
            const ulonglong2* wv = (const ulonglong2*)(s_w1t + k*128 + c0);
#pragma unroll
            for (int i = 0; i < 4; i++) {
                ulonglong2 w = wv[i];
                acc1[0][2*i]   = fma2(a0, w.x, acc1[0][2*i]);
                acc1[0][2*i+1] = fma2(a0, w.y, acc1[0][2*i+1]);
                acc1[1][2*i]   = fma2(a1, w.x, acc1[1][2*i]);
                acc1[1][2*i+1] = fma2(a1, w.y, acc1[1][2*i+1]);
                acc1[2][2*i]   = fma2(a2, w.x, acc1[2][2*i]);
                acc1[2][2*i+1] = fma2(a2, w.y, acc1[2][2*i+1]);
                acc1[3][2*i]   = fma2(a3, w.x, acc1[3][2*i]);
                acc1[3][2*i+1] = fma2(a3, w.y, acc1[3][2*i+1]);
            }
        }

#pragma unroll
        for (int r = 0; r < 4; r++)
#pragma unroll
            for (int p = 0; p < 8; p++) {
                float l, h;
                unpack2(acc1[r][p], l, h);
                acc1[r][p] = pack2(fmaxf(l, 0.0f), fmaxf(h, 0.0f));
            }

        // ---- phase3: partial layer2 over this warp's 16 cols ----
        float part[4][4];
#pragma unroll
        for (int kk = 0; kk < 4; kk++) {
            const ulonglong2* w2v = (const ulonglong2*)(s_w2 + kk*128 + c0);
            ull wp[8];
#pragma unroll
            for (int i = 0; i < 4; i++) {
                ulonglong2 v = w2v[i];
                wp[2*i] = v.x; wp[2*i+1] = v.y;
            }
#pragma unroll
            for (int r = 0; r < 4; r++) {
                ull s0 = 0ull, s1 = 0ull;
#pragma unroll
                for (int p = 0; p < 4; p++) {
                    s0 = fma2(acc1[r][2*p],   wp[2*p],   s0);
                    s1 = fma2(acc1[r][2*p+1], wp[2*p+1], s1);
                }
                float a, b, c, d;
                unpack2(s0, a, b);
                unpack2(s1, c, d);
                part[r][kk] = (a + b) + (c + d);
            }
        }
#pragma unroll
        for (int r = 0; r < 4; r++)
            *(float4*)(s_red + (size_t)(cg*128 + r0 + r) * 4) =
                make_float4(part[r][0], part[r][1], part[r][2], part[r][3]);
        __syncthreads();

        // ---- reduce across 8 warps, relu, permute, store ----
        if (tid < 128) {
            float o0 = s_b2[0], o1 = s_b2[1], o2 = s_b2[2], o3 = s_b2[3];
#pragma unroll
            for (int g = 0; g < 8; g++) {
                float4 v = *(const float4*)(s_red + (size_t)(g*128 + tid) * 4);
                o0 += v.x; o1 += v.y; o2 += v.z; o3 += v.w;
            }
            o0 = fmaxf(o0, 0.0f); o1 = fmaxf(o1, 0.0f);
            o2 = fmaxf(o2, 0.0f); o3 = fmaxf(o3, 0.0f);
            // raw = concat(net[...,1:4], net[...,0:1])
            ((float4*)out)[rowBase + tid] = make_float4(o1, o2, o3, o0);
        }
        __syncthreads();
    }
}

// ---------------------------------------------------------------------------
extern "C" void kernel_launch(void* const* d_in, const int* in_sizes, int n_in,
                              void* d_out, int out_size) {
    const float* coords = (const float*)d_in[0];
    const float* tri    = (const float*)d_in[1];
    const float* w0     = (const float*)d_in[2];
    const float* b0     = (const float*)d_in[3];
    const float* w1     = (const float*)d_in[4];
    const float* b1     = (const float*)d_in[5];
    const float* w2     = (const float*)d_in[6];
    const float* b2     = (const float*)d_in[7];
    float* out = (float*)d_out;

    int total = in_sizes[0] / 3;   // B * N points = MLP rows

    transpose_kernel<<<(3 * HH * WW + 127) / 128, 128>>>(tri);

    // 32 points per 256-thread block (8 threads per point)
    sample_kernel<<<total / 32, 256>>>(coords);

    int mlp_smem = SMEM_FLOATS * 4;   // ~179 KB dynamic shared
    cudaFuncSetAttribute(mlp_kernel,
                         cudaFuncAttributeMaxDynamicSharedMemorySize, mlp_smem);
    mlp_kernel<<<148, 256, mlp_smem>>>(w0, b0, w1, b1, w2, b2, out, total);
}